// round 1
// baseline (speedup 1.0000x reference)
#include <cuda_runtime.h>
#include <cstdint>

#define RB   64
#define RT   512
#define RD   1024
#define RACT 1024
#define RM   (RT * RB)          // 32768 rows
#define NBLK_REC 128            // persistent grid (<=148 SMs, co-resident)
#define KSPLIT   16             // K-slices in recurrence (1024/64)

// ---------------- scratch (device globals: allocation-free) ----------------
__device__ float g_U[RT * RB * RACT];        // U[t][b][i]  (128 MB)
__device__ float g_A[RT * RB * RACT];        // a_t[t][b][i] (128 MB)
__device__ float g_P[KSPLIT * RB * RACT];    // per-step K-split partials (4 MB)
__device__ float g_Azero[RB * RACT];         // static zeros = a_{-1}
__device__ unsigned int g_count;             // barrier arrive counter (returns to 0)
__device__ volatile unsigned int g_gen;      // barrier generation (monotonic)

__device__ __forceinline__ float4 ldcg4(const float* p) {
    return __ldcg(reinterpret_cast<const float4*>(p));
}

// ---------------- grid barrier (128 blocks, replay-safe) ----------------
__device__ __forceinline__ void grid_barrier() {
    __threadfence();            // publish this thread's prior writes to L2
    __syncthreads();
    if (threadIdx.x == 0) {
        unsigned gen = g_gen;
        unsigned old = atomicAdd(&g_count, 1u);
        if (old == NBLK_REC - 1) {
            g_count = 0;
            __threadfence();
            g_gen = gen + 1;
        } else {
            while (g_gen == gen) { __nanosleep(64); }
        }
    }
    __syncthreads();
    __threadfence();
}

// ---------------- generic C = A * B^T + bias GEMM (fp32) ----------------
// MODE 0:  A = X with row remap (m -> X row (m&63)*512 + (m>>6)),  C = g_U (row m)
// MODE 1:  A = g_A (row m),  C = Cext with row remap (m -> (m&63)*512 + (m>>6))
// M = 32768, N = 1024, K = 1024. BM=BN=128, BK=16, 256 threads, 8x8 microtile.
template <int MODE>
__global__ void __launch_bounds__(256) gemm_nt(const float* __restrict__ Aext,
                                               const float* __restrict__ Bm,
                                               const float* __restrict__ bias,
                                               float* __restrict__ Cext)
{
    __shared__ float As[16][132];   // [k][m], 132*4B = 16B-aligned rows
    __shared__ float Bs[16][132];   // [k][n]

    const float* Am = (MODE == 0) ? Aext : g_A;
    float*       Cm = (MODE == 0) ? g_U  : Cext;

    const int tid = threadIdx.x;
    const int n0  = blockIdx.x * 128;
    const int m0  = blockIdx.y * 128;
    const int ty  = tid >> 4;       // 0..15 -> rows ty*8..+8
    const int tx  = tid & 15;       // 0..15 -> cols tx*8..+8

    // load mapping: 512 float4 slots per tile per matrix; 2 per thread
    const int kv = (tid & 3) * 4;   // k sub-offset {0,4,8,12}
    const int r0 = tid >> 2;        // 0..63 ; rows r0 and r0+64

    const int gmA0 = m0 + r0, gmA1 = m0 + r0 + 64;
    const int rowA0 = (MODE == 0) ? ((gmA0 & 63) * RT + (gmA0 >> 6)) : gmA0;
    const int rowA1 = (MODE == 0) ? ((gmA1 & 63) * RT + (gmA1 >> 6)) : gmA1;
    const int rowB0 = n0 + r0;
    const int rowB1 = n0 + r0 + 64;

    float acc[8][8] = {};

    for (int kt = 0; kt < 64; ++kt) {
        const int k0 = kt * 16 + kv;
        float4 a0 = *reinterpret_cast<const float4*>(Am + (size_t)rowA0 * 1024 + k0);
        float4 a1 = *reinterpret_cast<const float4*>(Am + (size_t)rowA1 * 1024 + k0);
        float4 b0 = *reinterpret_cast<const float4*>(Bm + (size_t)rowB0 * 1024 + k0);
        float4 b1 = *reinterpret_cast<const float4*>(Bm + (size_t)rowB1 * 1024 + k0);

        __syncthreads();   // previous tile's compute done
        As[kv + 0][r0] = a0.x; As[kv + 1][r0] = a0.y; As[kv + 2][r0] = a0.z; As[kv + 3][r0] = a0.w;
        As[kv + 0][r0 + 64] = a1.x; As[kv + 1][r0 + 64] = a1.y; As[kv + 2][r0 + 64] = a1.z; As[kv + 3][r0 + 64] = a1.w;
        Bs[kv + 0][r0] = b0.x; Bs[kv + 1][r0] = b0.y; Bs[kv + 2][r0] = b0.z; Bs[kv + 3][r0] = b0.w;
        Bs[kv + 0][r0 + 64] = b1.x; Bs[kv + 1][r0 + 64] = b1.y; Bs[kv + 2][r0 + 64] = b1.z; Bs[kv + 3][r0 + 64] = b1.w;
        __syncthreads();

#pragma unroll
        for (int k = 0; k < 16; ++k) {
            float av[8], bv[8];
            *reinterpret_cast<float4*>(&av[0]) = *reinterpret_cast<const float4*>(&As[k][ty * 8]);
            *reinterpret_cast<float4*>(&av[4]) = *reinterpret_cast<const float4*>(&As[k][ty * 8 + 4]);
            *reinterpret_cast<float4*>(&bv[0]) = *reinterpret_cast<const float4*>(&Bs[k][tx * 8]);
            *reinterpret_cast<float4*>(&bv[4]) = *reinterpret_cast<const float4*>(&Bs[k][tx * 8 + 4]);
#pragma unroll
            for (int i = 0; i < 8; ++i)
#pragma unroll
                for (int j = 0; j < 8; ++j)
                    acc[i][j] += av[i] * bv[j];
        }
    }

    float bbias[8];
#pragma unroll
    for (int j = 0; j < 8; ++j) bbias[j] = bias[n0 + tx * 8 + j];

#pragma unroll
    for (int i = 0; i < 8; ++i) {
        const int gm   = m0 + ty * 8 + i;
        const int crow = (MODE == 0) ? gm : ((gm & 63) * RT + (gm >> 6));
        float* cp = Cm + (size_t)crow * 1024 + n0 + tx * 8;
        float4 o0, o1;
        o0.x = acc[i][0] + bbias[0]; o0.y = acc[i][1] + bbias[1];
        o0.z = acc[i][2] + bbias[2]; o0.w = acc[i][3] + bbias[3];
        o1.x = acc[i][4] + bbias[4]; o1.y = acc[i][5] + bbias[5];
        o1.z = acc[i][6] + bbias[6]; o1.w = acc[i][7] + bbias[7];
        *reinterpret_cast<float4*>(cp)     = o0;
        *reinterpret_cast<float4*>(cp + 4) = o1;
    }
}

// ---------------- persistent recurrence: a_t = U_t + a_{t-1} @ Waa^T ----------------
// 128 blocks = 8 N-tiles (128 cols) x 16 K-slices (64 k). 128 threads, 8x8 microtile.
// Phase 1: partials P[ks][b][i] = sum_{k in slice} a_{t-1}[b][k] * Waa[i][k]
// Phase 2: a_t[b][i] = U[t][b][i] + sum_ks P[ks][b][i]   (block bx owns 512 contiguous floats)
__global__ void __launch_bounds__(128) rnn_rec(const float* __restrict__ Waa)
{
    __shared__ float As[16][68];    // [k][b]   (68*4B rows: 16B aligned)
    __shared__ float Bs[16][132];   // [k][i_local]

    const int tid = threadIdx.x;
    const int bx  = blockIdx.x;     // 0..127
    const int nb  = bx & 7;         // N-tile
    const int ks  = bx >> 3;        // K-slice
    const int n0  = nb * 128;
    const int ksl0 = ks * 64;

    const int tm = tid >> 4;        // 0..7  -> b rows tm*8..+8
    const int tx = tid & 15;        // 0..15 -> cols tx*8..+8

    const int kv  = (tid & 3) * 4;  // k sub-offset
    const int r0  = tid >> 2;       // 0..31

    for (int t = 0; t < RT; ++t) {
        const float* src = (t == 0) ? g_Azero : (g_A + (size_t)(t - 1) * (RB * RACT));
        float acc[8][8] = {};

        for (int kt = 0; kt < 4; ++kt) {
            const int kb = ksl0 + kt * 16 + kv;
            // A tile: 64 rows (b) x 16 k -> 256 float4 slots, 2/thread
            float4 a0 = *reinterpret_cast<const float4*>(src + (size_t)r0 * 1024 + kb);
            float4 a1 = *reinterpret_cast<const float4*>(src + (size_t)(r0 + 32) * 1024 + kb);
            // B tile: 128 rows (i) x 16 k -> 512 slots, 4/thread
            float4 w0 = *reinterpret_cast<const float4*>(Waa + (size_t)(n0 + r0)      * 1024 + kb);
            float4 w1 = *reinterpret_cast<const float4*>(Waa + (size_t)(n0 + r0 + 32) * 1024 + kb);
            float4 w2 = *reinterpret_cast<const float4*>(Waa + (size_t)(n0 + r0 + 64) * 1024 + kb);
            float4 w3 = *reinterpret_cast<const float4*>(Waa + (size_t)(n0 + r0 + 96) * 1024 + kb);

            __syncthreads();
            As[kv + 0][r0] = a0.x; As[kv + 1][r0] = a0.y; As[kv + 2][r0] = a0.z; As[kv + 3][r0] = a0.w;
            As[kv + 0][r0 + 32] = a1.x; As[kv + 1][r0 + 32] = a1.y; As[kv + 2][r0 + 32] = a1.z; As[kv + 3][r0 + 32] = a1.w;
            Bs[kv + 0][r0]      = w0.x; Bs[kv + 1][r0]      = w0.y; Bs[kv + 2][r0]      = w0.z; Bs[kv + 3][r0]      = w0.w;
            Bs[kv + 0][r0 + 32] = w1.x; Bs[kv + 1][r0 + 32] = w1.y; Bs[kv + 2][r0 + 32] = w1.z; Bs[kv + 3][r0 + 32] = w1.w;
            Bs[kv + 0][r0 + 64] = w2.x; Bs[kv + 1][r0 + 64] = w2.y; Bs[kv + 2][r0 + 64] = w2.z; Bs[kv + 3][r0 + 64] = w2.w;
            Bs[kv + 0][r0 + 96] = w3.x; Bs[kv + 1][r0 + 96] = w3.y; Bs[kv + 2][r0 + 96] = w3.z; Bs[kv + 3][r0 + 96] = w3.w;
            __syncthreads();

#pragma unroll
            for (int k = 0; k < 16; ++k) {
                float av[8], wv[8];
                *reinterpret_cast<float4*>(&av[0]) = *reinterpret_cast<const float4*>(&As[k][tm * 8]);
                *reinterpret_cast<float4*>(&av[4]) = *reinterpret_cast<const float4*>(&As[k][tm * 8 + 4]);
                *reinterpret_cast<float4*>(&wv[0]) = *reinterpret_cast<const float4*>(&Bs[k][tx * 8]);
                *reinterpret_cast<float4*>(&wv[4]) = *reinterpret_cast<const float4*>(&Bs[k][tx * 8 + 4]);
#pragma unroll
                for (int i = 0; i < 8; ++i)
#pragma unroll
                    for (int j = 0; j < 8; ++j)
                        acc[i][j] += av[i] * wv[j];
            }
        }

        // write partials
        float* Pp = g_P + (size_t)ks * (RB * RACT);
#pragma unroll
        for (int i = 0; i < 8; ++i) {
            const int b   = tm * 8 + i;
            float* pp = Pp + (size_t)b * 1024 + n0 + tx * 8;
            float4 o0, o1;
            o0.x = acc[i][0]; o0.y = acc[i][1]; o0.z = acc[i][2]; o0.w = acc[i][3];
            o1.x = acc[i][4]; o1.y = acc[i][5]; o1.z = acc[i][6]; o1.w = acc[i][7];
            *reinterpret_cast<float4*>(pp)     = o0;
            *reinterpret_cast<float4*>(pp + 4) = o1;
        }

        grid_barrier();

        // phase 2: reduce 16 partials + U  -> a_t  (512 floats per block)
        {
            const int base = (bx << 9) + (tid << 2);
            float4 s = *reinterpret_cast<const float4*>(g_U + (size_t)t * (RB * RACT) + base);
#pragma unroll
            for (int p = 0; p < KSPLIT; ++p) {
                float4 v = ldcg4(g_P + (size_t)p * (RB * RACT) + base);  // bypass stale L1
                s.x += v.x; s.y += v.y; s.z += v.z; s.w += v.w;
            }
            *reinterpret_cast<float4*>(g_A + (size_t)t * (RB * RACT) + base) = s;
        }

        grid_barrier();
    }
}

// ---------------- launch ----------------
extern "C" void kernel_launch(void* const* d_in, const int* in_sizes, int n_in,
                              void* d_out, int out_size)
{
    const float* X   = (const float*)d_in[0];
    const float* Wax = (const float*)d_in[1];
    const float* Waa = (const float*)d_in[2];
    const float* ba  = (const float*)d_in[3];
    const float* Wy  = (const float*)d_in[4];
    const float* by  = (const float*)d_in[5];
    float* out = (float*)d_out;

    dim3 gg(8, 256);   // N-tiles x M-tiles
    gemm_nt<0><<<gg, 256>>>(X, Wax, ba, nullptr);        // U = X @ Wax^T + ba   (rows t*64+b)
    rnn_rec<<<NBLK_REC, 128>>>(Waa);                     // a_t = U_t + a_{t-1} @ Waa^T
    gemm_nt<1><<<gg, 256>>>(nullptr, Wy, by, out);       // out[b][t][:] = a_t[b] @ Wy^T + by
}

// round 3
// speedup vs baseline: 1.6562x; 1.6562x over previous
#include <cuda_runtime.h>
#include <cuda_bf16.h>
#include <cstdint>

#define RB   64
#define RT   512
#define RACT 1024
#define RM   (RT * RB)          // 32768
#define NBLK_REC 128
#define KSPLIT   8              // recurrence K-slices (128 k each)
#define NTILES   16             // recurrence N-tiles (64 n each)

// ---------------- scratch (device globals: allocation-free) ----------------
__device__ __align__(256) float g_U[RM * RACT];          // U[t][b][i] fp32
__device__ __align__(256) float g_P[KSPLIT * RB * RACT]; // per-step partials
__device__ unsigned int g_count;
__device__ volatile unsigned int g_gen;

// bf16 hi/lo split buffers
__device__ __align__(256) __nv_bfloat16 g_Xhi[RM * RACT];
__device__ __align__(256) __nv_bfloat16 g_Xlo[RM * RACT];
__device__ __align__(256) __nv_bfloat16 g_Ahi[RM * RACT];   // a_t split (written by recurrence)
__device__ __align__(256) __nv_bfloat16 g_Alo[RM * RACT];
__device__ __align__(256) __nv_bfloat16 g_W1hi[RACT * RACT];  // Wax
__device__ __align__(256) __nv_bfloat16 g_W1lo[RACT * RACT];
__device__ __align__(256) __nv_bfloat16 g_W2hi[RACT * RACT];  // Wy
__device__ __align__(256) __nv_bfloat16 g_W2lo[RACT * RACT];
__device__ __align__(256) __nv_bfloat16 g_W3hi[RACT * RACT];  // Waa
__device__ __align__(256) __nv_bfloat16 g_W3lo[RACT * RACT];

// ---------------- PTX helpers (all portable: sm_80/75 features) ----------------
__device__ __forceinline__ uint32_t s2u(const void* p) {
    uint32_t a;
    asm("{ .reg .u64 t; cvta.to.shared.u64 t, %1; cvt.u32.u64 %0, t; }" : "=r"(a) : "l"(p));
    return a;
}
__device__ __forceinline__ void cpa16(uint32_t d, const void* s) {
    asm volatile("cp.async.cg.shared.global [%0], [%1], 16;\n" :: "r"(d), "l"(s));
}
__device__ __forceinline__ void cp_commit() { asm volatile("cp.async.commit_group;\n" ::: "memory"); }
template <int N> __device__ __forceinline__ void cp_wait() {
    asm volatile("cp.async.wait_group %0;\n" :: "n"(N) : "memory");
}
__device__ __forceinline__ void ldsm4(uint32_t& r0, uint32_t& r1, uint32_t& r2, uint32_t& r3,
                                      uint32_t addr) {
    asm volatile("ldmatrix.sync.aligned.m8n8.x4.shared.b16 {%0,%1,%2,%3}, [%4];"
                 : "=r"(r0), "=r"(r1), "=r"(r2), "=r"(r3) : "r"(addr));
}
__device__ __forceinline__ void mma16816(float* c, const uint32_t* a, const uint32_t* b) {
    asm volatile(
        "mma.sync.aligned.m16n8k16.row.col.f32.bf16.bf16.f32 "
        "{%0,%1,%2,%3}, {%4,%5,%6,%7}, {%8,%9}, {%0,%1,%2,%3};"
        : "+f"(c[0]), "+f"(c[1]), "+f"(c[2]), "+f"(c[3])
        : "r"(a[0]), "r"(a[1]), "r"(a[2]), "r"(a[3]), "r"(b[0]), "r"(b[1]));
}
__device__ __forceinline__ float4 ldcg4(const float* p) {
    return __ldcg(reinterpret_cast<const float4*>(p));
}

// ---------------- grid barrier (128 blocks, replay-safe) ----------------
__device__ __forceinline__ void grid_barrier() {
    __threadfence();
    __syncthreads();
    if (threadIdx.x == 0) {
        unsigned gen = g_gen;
        unsigned old = atomicAdd(&g_count, 1u);
        if (old == NBLK_REC - 1) {
            g_count = 0;
            __threadfence();
            g_gen = gen + 1;
        } else {
            while (g_gen == gen) { __nanosleep(64); }
        }
    }
    __syncthreads();
    __threadfence();
}

// ---------------- hi/lo split kernels ----------------
__device__ __forceinline__ unsigned short f2bh(float x) {
    return __bfloat16_as_ushort(__float2bfloat16(x));
}
__device__ __forceinline__ unsigned short f2bl(float x, unsigned short h) {
    return __bfloat16_as_ushort(__float2bfloat16(x - __bfloat162float(__ushort_as_bfloat16(h))));
}
// DST: 0 -> X, 1 -> Wax, 2 -> Wy, 3 -> Waa
template <int DST>
__global__ void split_in(const float4* __restrict__ src, int n4) {
    int i = blockIdx.x * blockDim.x + threadIdx.x;
    if (i >= n4) return;
    float4 v = src[i];
    ushort4 h, l;
    h.x = f2bh(v.x); l.x = f2bl(v.x, h.x);
    h.y = f2bh(v.y); l.y = f2bl(v.y, h.y);
    h.z = f2bh(v.z); l.z = f2bl(v.z, h.z);
    h.w = f2bh(v.w); l.w = f2bl(v.w, h.w);
    ushort4* hi = (DST == 0) ? (ushort4*)g_Xhi : (DST == 1) ? (ushort4*)g_W1hi
                : (DST == 2) ? (ushort4*)g_W2hi : (ushort4*)g_W3hi;
    ushort4* lo = (DST == 0) ? (ushort4*)g_Xlo : (DST == 1) ? (ushort4*)g_W1lo
                : (DST == 2) ? (ushort4*)g_W2lo : (ushort4*)g_W3lo;
    hi[i] = h; lo[i] = l;
}

// ---------------- HMMA GEMM: C[m][n] = sum_k A[m][k]*B[n][k] + bias[n] ----------------
// bf16x3: Ahi*Bhi + Ahi*Blo + Alo*Bhi, fp32 accumulators (register-resident).
// CTA 128m x 128n x 32k/stage, 3-stage cp.async, 8 warps (warp tile 64m x 32n).
// smem rows padded to 80B (5 x 16B) -> ldmatrix conflict-free.
// MODE 0: A = X split (row remap m -> (m&63)*512 + (m>>6)), B = Wax, C = g_U row m
// MODE 1: A = A split (row m),                              B = Wy,  C = Cext remapped
#define TILE_B  10240          // 128 rows x 80 B
#define STG_B   (4 * TILE_B)   // Ah, Al, Bh, Bl
#define GSMEM   (3 * STG_B)    // 122880

template <int MODE>
__global__ void __launch_bounds__(256, 1) gemm_mma(const float* __restrict__ bias,
                                                   float* __restrict__ Cext)
{
    extern __shared__ char smc[];
    const uint32_t sbase = s2u(smc);

    const __nv_bfloat16* Ahi = (MODE == 0) ? g_Xhi : g_Ahi;
    const __nv_bfloat16* Alo = (MODE == 0) ? g_Xlo : g_Alo;
    const __nv_bfloat16* Bhi = (MODE == 0) ? g_W1hi : g_W2hi;
    const __nv_bfloat16* Blo = (MODE == 0) ? g_W1lo : g_W2lo;
    float* Cm = (MODE == 0) ? g_U : Cext;

    const int tid  = threadIdx.x;
    const int wid  = tid >> 5, lane = tid & 31;
    const int n0   = blockIdx.x * 128, m0 = blockIdx.y * 128;
    const int wM   = (wid & 1) * 64;      // warp m offset
    const int wN   = (wid >> 1) * 32;     // warp n offset

    // per-thread cp.async mapping: 8 x 16B per stage
    const char* srcp[8];
    uint32_t dsto[8];
#pragma unroll
    for (int i = 0; i < 8; i++) {
        int idx = i * 256 + tid;
        int buf = idx >> 9;              // 0 Ah, 1 Al, 2 Bh, 3 Bl
        int r   = (idx >> 2) & 127;
        int s   = idx & 3;
        dsto[i] = (uint32_t)(buf * TILE_B + r * 80 + s * 16);
        size_t grow;
        const __nv_bfloat16* p;
        if (buf < 2) {
            int row = m0 + r;
            grow = (MODE == 0) ? (size_t)(((row & 63) << 9) | (row >> 6)) : (size_t)row;
            p = (buf == 0) ? Ahi : Alo;
        } else {
            grow = (size_t)(n0 + r);
            p = (buf == 2) ? Bhi : Blo;
        }
        srcp[i] = (const char*)p + grow * 2048 + s * 16;
    }

    // prologue: stages 0,1
#pragma unroll
    for (int st = 0; st < 2; st++) {
#pragma unroll
        for (int i = 0; i < 8; i++)
            cpa16(sbase + st * STG_B + dsto[i], srcp[i] + st * 64);
        cp_commit();
    }

    float acc[4][4][4];
#pragma unroll
    for (int a = 0; a < 4; a++)
#pragma unroll
        for (int b = 0; b < 4; b++)
#pragma unroll
            for (int c = 0; c < 4; c++) acc[a][b][c] = 0.f;

    const int j  = lane >> 3;
    const int arl = (lane & 7) + (j & 1) * 8;   // A ldmatrix row-in-tile16
    const int brl = (lane & 7) + (j >> 1) * 8;  // B ldmatrix row-in-tile16

    for (int c = 0; c < 32; c++) {
        cp_wait<1>();
        __syncthreads();
        if (c + 2 < 32) {
            uint32_t sb2 = sbase + ((c + 2) % 3) * STG_B;
#pragma unroll
            for (int i = 0; i < 8; i++)
                cpa16(sb2 + dsto[i], srcp[i] + (c + 2) * 64);
        }
        cp_commit();

        const uint32_t sb = sbase + (c % 3) * STG_B;
#pragma unroll
        for (int kt = 0; kt < 2; kt++) {
            const int aseg = kt * 2 + (j >> 1);
            const int bseg = kt * 2 + (j & 1);
            uint32_t ah[4][4], al[4][4];
#pragma unroll
            for (int mt = 0; mt < 4; mt++) {
                uint32_t ra = sb + (uint32_t)((wM + mt * 16 + arl) * 80 + aseg * 16);
                ldsm4(ah[mt][0], ah[mt][1], ah[mt][2], ah[mt][3], ra);
                ldsm4(al[mt][0], al[mt][1], al[mt][2], al[mt][3], ra + TILE_B);
            }
            uint32_t bh[4][2], bl[4][2];
#pragma unroll
            for (int bt = 0; bt < 2; bt++) {
                uint32_t rb = sb + 2 * TILE_B + (uint32_t)((wN + bt * 16 + brl) * 80 + bseg * 16);
                uint32_t t0, t1, t2, t3;
                ldsm4(t0, t1, t2, t3, rb);
                bh[bt * 2][0] = t0; bh[bt * 2][1] = t1;
                bh[bt * 2 + 1][0] = t2; bh[bt * 2 + 1][1] = t3;
                ldsm4(t0, t1, t2, t3, rb + TILE_B);
                bl[bt * 2][0] = t0; bl[bt * 2][1] = t1;
                bl[bt * 2 + 1][0] = t2; bl[bt * 2 + 1][1] = t3;
            }
#pragma unroll
            for (int mt = 0; mt < 4; mt++)
#pragma unroll
                for (int nt = 0; nt < 4; nt++) {
                    mma16816(acc[mt][nt], ah[mt], bh[nt]);
                    mma16816(acc[mt][nt], ah[mt], bl[nt]);
                    mma16816(acc[mt][nt], al[mt], bh[nt]);
                }
        }
    }

    // epilogue
    float2 bb[4];
#pragma unroll
    for (int nt = 0; nt < 4; nt++) {
        int col = n0 + wN + nt * 8 + (lane & 3) * 2;
        bb[nt].x = bias[col]; bb[nt].y = bias[col + 1];
    }
#pragma unroll
    for (int mt = 0; mt < 4; mt++)
#pragma unroll
        for (int h = 0; h < 2; h++) {
            int row  = m0 + wM + mt * 16 + (lane >> 2) + h * 8;
            size_t crow = (MODE == 0) ? (size_t)row
                                      : (size_t)(((row & 63) << 9) | (row >> 6));
#pragma unroll
            for (int nt = 0; nt < 4; nt++) {
                int col = n0 + wN + nt * 8 + (lane & 3) * 2;
                float2 v;
                v.x = acc[mt][nt][h * 2]     + bb[nt].x;
                v.y = acc[mt][nt][h * 2 + 1] + bb[nt].y;
                *reinterpret_cast<float2*>(Cm + crow * 1024 + col) = v;
            }
        }
}

// ---------------- HMMA recurrence: a_t = U_t + a_{t-1} @ Waa^T ----------------
// 128 blocks = 16 N-tiles (64 n) x 8 K-slices (128 k), 128 threads (4 warps, warp = 16 n).
// Waa hi/lo slice cached in smem once. Per step: cp.async a_{t-1} hi/lo slice,
// 192 HMMA/warp -> fp32 partials, barrier, reduce 8 partials + U -> emit bf16 hi/lo.
#define RROW 272                // 128 k bf16 = 256B data, padded to 17 x 16B
#define R_AH 0
#define R_AL (64 * RROW)
#define R_WH (2 * 64 * RROW)
#define R_WL (3 * 64 * RROW)
#define RSMEM (4 * 64 * RROW)   // 69632

__global__ void __launch_bounds__(128, 1) rnn_rec_mma()
{
    extern __shared__ char smc[];
    const uint32_t sbase = s2u(smc);

    const int tid = threadIdx.x, wid = tid >> 5, lane = tid & 31;
    const int bx  = blockIdx.x;
    const int nb  = bx & 15, ks = bx >> 4;
    const int n0  = nb * 64;
    const int kb0 = ks * 256;          // byte offset of K-slice in a 2048B row

    // load Waa hi/lo slice once (2048 x 16B / 128 thr = 16 per thread)
#pragma unroll
    for (int i = 0; i < 16; i++) {
        int idx = i * 128 + tid;
        int buf = idx >> 10, r = (idx >> 4) & 63, s = idx & 15;
        uint32_t dst = sbase + (buf ? R_WL : R_WH) + (uint32_t)(r * RROW + s * 16);
        const char* src = (const char*)(buf ? g_W3lo : g_W3hi)
                        + (size_t)(n0 + r) * 2048 + kb0 + s * 16;
        cpa16(dst, src);
    }
    cp_commit();
    cp_wait<0>();
    __syncthreads();

    const int j   = lane >> 3;
    const int arl = (lane & 7) + (j & 1) * 8;
    const int brl = (lane & 7) + (j >> 1) * 8;
    float* Pp = g_P + (size_t)ks * (RB * RACT);

    for (int t = 0; t < RT; ++t) {
        if (t > 0) {
            // stream a_{t-1} hi/lo slice: 64 rows x 256B x2
#pragma unroll
            for (int i = 0; i < 16; i++) {
                int idx = i * 128 + tid;
                int buf = idx >> 10, r = (idx >> 4) & 63, s = idx & 15;
                uint32_t dst = sbase + (buf ? R_AL : R_AH) + (uint32_t)(r * RROW + s * 16);
                const char* src = (const char*)(buf ? g_Alo : g_Ahi)
                                + (size_t)((t - 1) * 64 + r) * 2048 + kb0 + s * 16;
                cpa16(dst, src);
            }
            cp_commit();
            cp_wait<0>();
            __syncthreads();

            float acc[4][2][4];
#pragma unroll
            for (int a = 0; a < 4; a++)
#pragma unroll
                for (int b = 0; b < 2; b++)
#pragma unroll
                    for (int c = 0; c < 4; c++) acc[a][b][c] = 0.f;

#pragma unroll
            for (int kt = 0; kt < 8; kt++) {
                const int aseg = kt * 2 + (j >> 1);
                const int bseg = kt * 2 + (j & 1);
                uint32_t ah[4][4], al[4][4];
#pragma unroll
                for (int mt = 0; mt < 4; mt++) {
                    uint32_t ra = sbase + R_AH + (uint32_t)((mt * 16 + arl) * RROW + aseg * 16);
                    ldsm4(ah[mt][0], ah[mt][1], ah[mt][2], ah[mt][3], ra);
                    ldsm4(al[mt][0], al[mt][1], al[mt][2], al[mt][3], ra + (R_AL - R_AH));
                }
                uint32_t bh[2][2], bl[2][2];
                {
                    uint32_t rb = sbase + R_WH + (uint32_t)((wid * 16 + brl) * RROW + bseg * 16);
                    uint32_t t0, t1, t2, t3;
                    ldsm4(t0, t1, t2, t3, rb);
                    bh[0][0] = t0; bh[0][1] = t1; bh[1][0] = t2; bh[1][1] = t3;
                    ldsm4(t0, t1, t2, t3, rb + (R_WL - R_WH));
                    bl[0][0] = t0; bl[0][1] = t1; bl[1][0] = t2; bl[1][1] = t3;
                }
#pragma unroll
                for (int mt = 0; mt < 4; mt++)
#pragma unroll
                    for (int nt = 0; nt < 2; nt++) {
                        mma16816(acc[mt][nt], ah[mt], bh[nt]);
                        mma16816(acc[mt][nt], ah[mt], bl[nt]);
                        mma16816(acc[mt][nt], al[mt], bh[nt]);
                    }
            }

            // partials: P[ks][b][i]
#pragma unroll
            for (int mt = 0; mt < 4; mt++)
#pragma unroll
                for (int h = 0; h < 2; h++) {
                    int b = mt * 16 + (lane >> 2) + h * 8;
#pragma unroll
                    for (int nt = 0; nt < 2; nt++) {
                        int icol = n0 + wid * 16 + nt * 8 + (lane & 3) * 2;
                        float2 v;
                        v.x = acc[mt][nt][h * 2];
                        v.y = acc[mt][nt][h * 2 + 1];
                        *reinterpret_cast<float2*>(Pp + (size_t)b * 1024 + icol) = v;
                    }
                }
        }

        grid_barrier();

        // phase 2: a_t = U_t + sum partials; emit bf16 hi/lo
        {
            const int base = bx * 512 + tid * 4;
            float4 s4 = *reinterpret_cast<const float4*>(g_U + (size_t)t * (RB * RACT) + base);
            if (t > 0) {
#pragma unroll
                for (int p = 0; p < KSPLIT; ++p) {
                    float4 v = ldcg4(g_P + (size_t)p * (RB * RACT) + base);
                    s4.x += v.x; s4.y += v.y; s4.z += v.z; s4.w += v.w;
                }
            }
            ushort4 h4, l4;
            h4.x = f2bh(s4.x); l4.x = f2bl(s4.x, h4.x);
            h4.y = f2bh(s4.y); l4.y = f2bl(s4.y, h4.y);
            h4.z = f2bh(s4.z); l4.z = f2bl(s4.z, h4.z);
            h4.w = f2bh(s4.w); l4.w = f2bl(s4.w, h4.w);
            const size_t e = (size_t)t * (RB * RACT) + base;
            *reinterpret_cast<ushort4*>(&g_Ahi[e]) = h4;
            *reinterpret_cast<ushort4*>(&g_Alo[e]) = l4;
        }

        grid_barrier();
    }
}

// ---------------- launch ----------------
extern "C" void kernel_launch(void* const* d_in, const int* in_sizes, int n_in,
                              void* d_out, int out_size)
{
    const float* X   = (const float*)d_in[0];
    const float* Wax = (const float*)d_in[1];
    const float* Waa = (const float*)d_in[2];
    const float* ba  = (const float*)d_in[3];
    const float* Wy  = (const float*)d_in[4];
    const float* by  = (const float*)d_in[5];
    float* out = (float*)d_out;

    cudaFuncSetAttribute(gemm_mma<0>, cudaFuncAttributeMaxDynamicSharedMemorySize, GSMEM);
    cudaFuncSetAttribute(gemm_mma<1>, cudaFuncAttributeMaxDynamicSharedMemorySize, GSMEM);
    cudaFuncSetAttribute(rnn_rec_mma, cudaFuncAttributeMaxDynamicSharedMemorySize, RSMEM);

    const int n4x = RM * RACT / 4;
    const int n4w = RACT * RACT / 4;

    split_in<0><<<n4x / 256, 256>>>((const float4*)X, n4x);
    split_in<1><<<n4w / 256, 256>>>((const float4*)Wax, n4w);
    split_in<2><<<n4w / 256, 256>>>((const float4*)Wy, n4w);
    split_in<3><<<n4w / 256, 256>>>((const float4*)Waa, n4w);

    gemm_mma<0><<<dim3(8, 256), 256, GSMEM>>>(ba, nullptr);   // U = X @ Wax^T + ba
    rnn_rec_mma<<<NBLK_REC, 128, RSMEM>>>();                  // a_t (bf16 hi/lo)
    gemm_mma<1><<<dim3(8, 256), 256, GSMEM>>>(by, out);       // out = A @ Wy^T + by
}